// round 3
// baseline (speedup 1.0000x reference)
#include <cuda_runtime.h>
#include <math.h>

#define BQ 32     // batch
#define SQ 32     // query tokens
#define HD 128    // hidden
#define CD 512    // docs
#define DD 128    // doc tokens
#define HC 64     // h chunk held in smem
#define QPITCH 36 // Qs row pitch (16B aligned, != mult of 32 banks)
#define INV_TEMP 50.0f   // 1/0.02

// scores[b][c], written by kernel 1, consumed by kernel 2 (no allocations allowed)
__device__ float g_scores[BQ * CD];

// packed fp32x2 FMA: d = a*b + d  (two independent fp32 lanes, rn)
__device__ __forceinline__ void ffma2(unsigned long long& d,
                                      unsigned long long a,
                                      unsigned long long b) {
    asm("fma.rn.f32x2 %0, %1, %2, %0;" : "+l"(d) : "l"(a), "l"(b));
}
__device__ __forceinline__ unsigned long long pack2(float x, float y) {
    unsigned long long p;
    asm("mov.b64 %0, {%1, %2};" : "=l"(p) : "f"(x), "f"(y));
    return p;
}
__device__ __forceinline__ void unpack2(unsigned long long p, float& x, float& y) {
    asm("mov.b64 {%0, %1}, %2;" : "=f"(x), "=f"(y) : "l"(p));
}

// ---------------------------------------------------------------------------
// Kernel 1: one CTA per (b, c).
//   scores[b][c] = (sum_s max_d dot(Q[b,s,:], P[c,d,:])) / T
// 128 threads, each owns 4(s) x 8(d) accumulators held as 4x4 f32x2 pairs,
// outer-product over h with packed FFMA2 (2 fp32 FMA per issue).
// ---------------------------------------------------------------------------
__global__ __launch_bounds__(128, 5)
void maxsim_kernel(const float* __restrict__ Q, const float* __restrict__ P) {
    const int b = blockIdx.y;
    const int c = blockIdx.x;

    __shared__ __align__(16) float Qs[HC][QPITCH];  // [h][s]
    __shared__ __align__(16) float Ps[HC][128];     // [h][d_swizzled]
    __shared__ float smax[SQ];

    const int tid = threadIdx.x;
    const int dx  = tid & 15;    // 16 thread-columns over d (8 d each)
    const int sy  = tid >> 4;    // 8 thread-rows over s (4 s each)

    unsigned long long acc[4][4];  // [s][d-pair], each holds 2 fp32
#pragma unroll
    for (int i = 0; i < 4; ++i)
#pragma unroll
        for (int j = 0; j < 4; ++j) acc[i][j] = 0ull;

    const float* Qb = Q + (size_t)b * (SQ * HD);
    const float* Pc = P + (size_t)c * (DD * HD);

    for (int hc = 0; hc < HD; hc += HC) {
        __syncthreads();  // previous chunk fully consumed before overwrite

        // ---- load Q chunk: 32 s x 64 h -> Qs[h][s] (transposed) ----
#pragma unroll
        for (int k = 0; k < 4; ++k) {
            int i   = tid + k * 128;         // 0..511
            int hh4 = i & 15;                // float4 index along h
            int s   = i >> 4;                // 0..31
            float4 v = *reinterpret_cast<const float4*>(Qb + s * HD + hc + hh4 * 4);
            int r = hh4 * 4;
            Qs[r + 0][s] = v.x;
            Qs[r + 1][s] = v.y;
            Qs[r + 2][s] = v.z;
            Qs[r + 3][s] = v.w;
        }

        // ---- load P chunk: 128 d x 64 h -> Ps[h][swz(d)] (transposed+swizzled) ----
#pragma unroll
        for (int k = 0; k < 16; ++k) {
            int i   = tid + k * 128;         // 0..2047
            int hh4 = i & 15;
            int d   = i >> 4;                // 0..127
            float4 v = *reinterpret_cast<const float4*>(Pc + d * HD + hc + hh4 * 4);
            int swz = ((((d >> 2) ^ (hh4 & 7)) << 2) | (d & 3));
            int r = hh4 * 4;
            Ps[r + 0][swz] = v.x;
            Ps[r + 1][swz] = v.y;
            Ps[r + 2][swz] = v.z;
            Ps[r + 3][swz] = v.w;
        }
        __syncthreads();

        // ---- outer-product accumulation over this h chunk (packed f32x2) ----
#pragma unroll 8
        for (int h = 0; h < HC; ++h) {
            const int cswz = (h >> 2) & 7;
            float4 a4 = *reinterpret_cast<const float4*>(&Qs[h][sy * 4]);
            float4 b0 = *reinterpret_cast<const float4*>(&Ps[h][(dx ^ cswz) << 2]);
            float4 b1 = *reinterpret_cast<const float4*>(&Ps[h][((16 + dx) ^ cswz) << 2]);

            unsigned long long pa0 = pack2(a4.x, a4.x);
            unsigned long long pa1 = pack2(a4.y, a4.y);
            unsigned long long pa2 = pack2(a4.z, a4.z);
            unsigned long long pa3 = pack2(a4.w, a4.w);

            unsigned long long pb0 = pack2(b0.x, b0.y);
            unsigned long long pb1 = pack2(b0.z, b0.w);
            unsigned long long pb2 = pack2(b1.x, b1.y);
            unsigned long long pb3 = pack2(b1.z, b1.w);

            ffma2(acc[0][0], pa0, pb0); ffma2(acc[0][1], pa0, pb1);
            ffma2(acc[0][2], pa0, pb2); ffma2(acc[0][3], pa0, pb3);
            ffma2(acc[1][0], pa1, pb0); ffma2(acc[1][1], pa1, pb1);
            ffma2(acc[1][2], pa1, pb2); ffma2(acc[1][3], pa1, pb3);
            ffma2(acc[2][0], pa2, pb0); ffma2(acc[2][1], pa2, pb1);
            ffma2(acc[2][2], pa2, pb2); ffma2(acc[2][3], pa2, pb3);
            ffma2(acc[3][0], pa3, pb0); ffma2(acc[3][1], pa3, pb1);
            ffma2(acc[3][2], pa3, pb2); ffma2(acc[3][3], pa3, pb3);
        }
    }

    // ---- max over d (thread-local 8, then across the 16 d-threads) ----
    float m[4];
#pragma unroll
    for (int i = 0; i < 4; ++i) {
        float v = -3.402823e38f;
#pragma unroll
        for (int j = 0; j < 4; ++j) {
            float x, y;
            unpack2(acc[i][j], x, y);
            v = fmaxf(v, fmaxf(x, y));
        }
        m[i] = v;
    }
#pragma unroll
    for (int off = 1; off < 16; off <<= 1) {
#pragma unroll
        for (int i = 0; i < 4; ++i)
            m[i] = fmaxf(m[i], __shfl_xor_sync(0xffffffffu, m[i], off));
    }
    if (dx == 0) {
#pragma unroll
        for (int i = 0; i < 4; ++i) smax[sy * 4 + i] = m[i];
    }
    __syncthreads();

    // ---- sum over s, scale by 1/T ----
    if (tid < 32) {
        float v = smax[tid];
#pragma unroll
        for (int off = 16; off; off >>= 1) v += __shfl_xor_sync(0xffffffffu, v, off);
        if (tid == 0) g_scores[b * CD + c] = v * INV_TEMP;
    }
}

// ---------------------------------------------------------------------------
// Kernel 2: loss = mean_b( logsumexp_c(scores[b,:]) - scores[b,0] )
// 32 warps, one warp per batch row; float4 loads.
// ---------------------------------------------------------------------------
__global__ __launch_bounds__(1024)
void loss_kernel(float* __restrict__ out) {
    const int w    = threadIdx.x >> 5;
    const int lane = threadIdx.x & 31;
    const float* row = g_scores + w * CD;

    float4 v4[4];
#pragma unroll
    for (int k = 0; k < 4; ++k)
        v4[k] = *reinterpret_cast<const float4*>(row + (lane + k * 32) * 4);

    float mx = -3.402823e38f;
#pragma unroll
    for (int k = 0; k < 4; ++k)
        mx = fmaxf(mx, fmaxf(fmaxf(v4[k].x, v4[k].y), fmaxf(v4[k].z, v4[k].w)));
#pragma unroll
    for (int off = 16; off; off >>= 1) mx = fmaxf(mx, __shfl_xor_sync(0xffffffffu, mx, off));

    float se = 0.0f;
#pragma unroll
    for (int k = 0; k < 4; ++k) {
        se += expf(v4[k].x - mx) + expf(v4[k].y - mx)
            + expf(v4[k].z - mx) + expf(v4[k].w - mx);
    }
#pragma unroll
    for (int off = 16; off; off >>= 1) se += __shfl_xor_sync(0xffffffffu, se, off);

    __shared__ float part[32];
    if (lane == 0) part[w] = mx + logf(se) - row[0];
    __syncthreads();

    if (w == 0) {
        float v = part[lane];
#pragma unroll
        for (int off = 16; off; off >>= 1) v += __shfl_xor_sync(0xffffffffu, v, off);
        if (lane == 0) out[0] = v * (1.0f / (float)BQ);
    }
}

extern "C" void kernel_launch(void* const* d_in, const int* in_sizes, int n_in,
                              void* d_out, int out_size) {
    const float* Q = (const float*)d_in[0];
    const float* P = (const float*)d_in[1];
    if (n_in >= 2 && in_sizes[0] != BQ * SQ * HD) {
        const float* t = Q; Q = P; P = t;
    }
    float* out = (float*)d_out;

    dim3 grid(CD, BQ);
    maxsim_kernel<<<grid, 128>>>(Q, P);
    loss_kernel<<<1, 1024>>>(out);
}

// round 5
// speedup vs baseline: 3.2804x; 3.2804x over previous
#include <cuda_runtime.h>
#include <cuda_bf16.h>
#include <stdint.h>
#include <math.h>

#define BQ 32
#define SQ 32
#define HD 128
#define CD 512
#define DD 128
#define NGRP 8            // 8 groups of 4 batches (M=128 rows of A)
#define CPER 32           // docs per CTA
#define NCHUNK (CD/CPER)  // 16
#define INV_TEMP 50.0f

#define TILE64K 65536
#define SMEM_BYTES (3 * TILE64K)   // A (64KB) + 2 B stages (64KB each)

__device__ float g_scores[BQ * CD];
__device__ __align__(1024) unsigned char g_P_sw[(size_t)CD * TILE64K];   // 32 MB, B-fragment layout
__device__ __align__(1024) unsigned char g_Q_sw[(size_t)NGRP * TILE64K]; // 512 KB, A-fragment layout

// ---------------------------------------------------------------- PTX helpers
__device__ __forceinline__ uint32_t smem_u32(const void* p) {
    uint32_t a;
    asm("{ .reg .u64 t; cvta.to.shared.u64 t, %1; cvt.u32.u64 %0, t; }" : "=r"(a) : "l"(p));
    return a;
}
__device__ __forceinline__ void mbar_init(uint32_t m, uint32_t cnt) {
    asm volatile("mbarrier.init.shared.b64 [%0], %1;" :: "r"(m), "r"(cnt) : "memory");
}
__device__ __forceinline__ void mbar_expect_tx(uint32_t m, uint32_t bytes) {
    asm volatile("mbarrier.arrive.expect_tx.shared.b64 _, [%0], %1;" :: "r"(m), "r"(bytes) : "memory");
}
__device__ __forceinline__ void mbar_arrive(uint32_t m) {
    asm volatile("mbarrier.arrive.shared.b64 _, [%0];" :: "r"(m) : "memory");
}
__device__ __forceinline__ void mbar_wait(uint32_t m, uint32_t parity) {
    uint32_t done;
    asm volatile("{\n\t.reg .pred p;\n\t"
        "mbarrier.try_wait.parity.acquire.cta.shared::cta.b64 p, [%1], %2;\n\t"
        "selp.b32 %0, 1, 0, p;\n\t}"
        : "=r"(done) : "r"(m), "r"(parity) : "memory");
    while (!done) {
        asm volatile("{\n\t.reg .pred p;\n\t"
            "mbarrier.try_wait.parity.acquire.cta.shared::cta.b64 p, [%1], %2, 0x989680;\n\t"
            "selp.b32 %0, 1, 0, p;\n\t}"
            : "=r"(done) : "r"(m), "r"(parity) : "memory");
    }
}
__device__ __forceinline__ void bulk_copy_g2s(uint32_t dst, const void* src, uint32_t bytes, uint32_t mbar) {
    asm volatile("cp.async.bulk.shared::cluster.global.mbarrier::complete_tx::bytes [%0], [%1], %2, [%3];"
        :: "r"(dst), "l"(src), "r"(bytes), "r"(mbar) : "memory");
}
// warp mma: D(f32 16x8) += A(bf16 16x16, row) * B(bf16 16x8, col)
__device__ __forceinline__ void mma_bf16(float* c, const uint32_t* a, const uint32_t* b) {
    asm volatile("mma.sync.aligned.m16n8k16.row.col.f32.bf16.bf16.f32 "
        "{%0,%1,%2,%3}, {%4,%5,%6,%7}, {%8,%9}, {%0,%1,%2,%3};"
        : "+f"(c[0]), "+f"(c[1]), "+f"(c[2]), "+f"(c[3])
        : "r"(a[0]), "r"(a[1]), "r"(a[2]), "r"(a[3]), "r"(b[0]), "r"(b[1]));
}

__device__ __forceinline__ uint32_t bf16x2_hi(float f0, float f1, uint32_t& lo_out) {
    __nv_bfloat16 h0 = __float2bfloat16(f0);
    __nv_bfloat16 h1 = __float2bfloat16(f1);
    __nv_bfloat16 l0 = __float2bfloat16(f0 - __bfloat162float(h0));
    __nv_bfloat16 l1 = __float2bfloat16(f1 - __bfloat162float(h1));
    unsigned short uh0 = *reinterpret_cast<unsigned short*>(&h0);
    unsigned short uh1 = *reinterpret_cast<unsigned short*>(&h1);
    unsigned short ul0 = *reinterpret_cast<unsigned short*>(&l0);
    unsigned short ul1 = *reinterpret_cast<unsigned short*>(&l1);
    lo_out = (uint32_t)ul0 | ((uint32_t)ul1 << 16);
    return (uint32_t)uh0 | ((uint32_t)uh1 << 16);
}

// ---------------------------------------------------------------------------
// convert_P: P[c][d][h] f32 -> per-doc 64KB B-fragment blocks:
//   hi (32KB): word at ((k*16 + n)*32 + lane)*8 + ri*4 holds elements
//     (h = k*16 + ri*8 + (lane&3)*2 {,+1}, d = n*8 + (lane>>2))
//   lo at +32768.
// One thread per output word pair (hi+lo). idx < CD*8192.
// ---------------------------------------------------------------------------
__global__ void convert_P_kernel(const float* __restrict__ P) {
    int idx = blockIdx.x * blockDim.x + threadIdx.x;
    if (idx >= CD * 8192) return;
    int ri   = idx & 1;
    int lane = (idx >> 1) & 31;
    int n    = (idx >> 6) & 15;
    int k    = (idx >> 10) & 7;
    int c    = idx >> 13;
    int tg = lane & 3, gr = lane >> 2;
    int d = n * 8 + gr;
    int h = k * 16 + ri * 8 + tg * 2;

    const float* s = P + ((size_t)c * DD + d) * HD + h;
    uint32_t lo, hi = bf16x2_hi(s[0], s[1], lo);

    size_t off = (size_t)c * TILE64K + (size_t)(((k * 16 + n) * 32 + lane) * 8 + ri * 4);
    *reinterpret_cast<uint32_t*>(g_P_sw + off)         = hi;
    *reinterpret_cast<uint32_t*>(g_P_sw + off + 32768) = lo;
}

// ---------------------------------------------------------------------------
// convert_Q: Q[b][s][h] f32 -> per-group 64KB A-fragment blocks:
//   batch (16KB) { hi 8KB: word at ((m*8+k)*32+lane)*16 + ri*4 holds elements
//     (s = m*16 + (lane>>2) + (ri&1)*8, h = k*16 + (lane&3)*2 + (ri>>1)*8 {,+1})
//     lo at +8192 }
// idx < NGRP*8192.
// ---------------------------------------------------------------------------
__global__ void convert_Q_kernel(const float* __restrict__ Q) {
    int idx = blockIdx.x * blockDim.x + threadIdx.x;
    if (idx >= NGRP * 8192) return;
    int ri    = idx & 3;
    int lane  = (idx >> 2) & 31;
    int k     = (idx >> 7) & 7;
    int m     = (idx >> 10) & 1;
    int batch = (idx >> 11) & 3;
    int g     = idx >> 13;
    int tg = lane & 3, gr = lane >> 2;
    int srow = m * 16 + gr + (ri & 1) * 8;
    int h    = k * 16 + tg * 2 + (ri >> 1) * 8;
    int b    = g * 4 + batch;

    const float* s = Q + ((size_t)b * SQ + srow) * HD + h;
    uint32_t lo, hi = bf16x2_hi(s[0], s[1], lo);

    size_t off = (size_t)g * TILE64K + (size_t)batch * 16384
               + (size_t)(((m * 8 + k) * 32 + lane) * 16 + ri * 4);
    *reinterpret_cast<uint32_t*>(g_Q_sw + off)        = hi;
    *reinterpret_cast<uint32_t*>(g_Q_sw + off + 8192) = lo;
}

// ---------------------------------------------------------------------------
// maxsim: grid (NCHUNK, NGRP), 256 threads, 1 CTA/SM.
// warp w: batch = w>>1 (of the group's 4), d-half = w&1 (64 of 128 d tokens).
// A resident in smem; B double-buffered 64KB stages via cp.async.bulk.
// 3-term bf16 split: acc += Ah*Bh + Ah*Bl + Al*Bh.
// ---------------------------------------------------------------------------
__global__ __launch_bounds__(256, 1)
void maxsim_kernel() {
    extern __shared__ __align__(128) unsigned char dyn[];
    __shared__ __align__(8) unsigned long long bars[5];  // QFULL, BFULL[2], BFREE[2]
    __shared__ float smax[2][4][2][32];

    const int tid = threadIdx.x, w = tid >> 5, lane = tid & 31;
    const int batch = w >> 1, dhalf = w & 1;
    const int tg = lane & 3, gr = lane >> 2;
    const int g = blockIdx.y;
    const int cbase = blockIdx.x * CPER;
    const int b = g * 4 + batch;

    const uint32_t QFULL = smem_u32(&bars[0]);
    const uint32_t BFULL0 = smem_u32(&bars[1]);
    const uint32_t BFREE0 = smem_u32(&bars[3]);

    if (tid == 0) {
        mbar_init(QFULL, 1);
        mbar_init(BFULL0, 1);     mbar_init(BFULL0 + 8, 1);
        mbar_init(BFREE0, 8);     mbar_init(BFREE0 + 8, 8);
    }
    __syncthreads();

    if (tid == 0) {
        mbar_expect_tx(QFULL, TILE64K);
        bulk_copy_g2s(smem_u32(dyn), g_Q_sw + (size_t)g * TILE64K, TILE64K, QFULL);
        mbar_expect_tx(BFULL0, TILE64K);
        bulk_copy_g2s(smem_u32(dyn + TILE64K), g_P_sw + (size_t)(cbase + 0) * TILE64K, TILE64K, BFULL0);
        mbar_expect_tx(BFULL0 + 8, TILE64K);
        bulk_copy_g2s(smem_u32(dyn + 2 * TILE64K), g_P_sw + (size_t)(cbase + 1) * TILE64K, TILE64K, BFULL0 + 8);
    }
    mbar_wait(QFULL, 0);

    const unsigned char* aBase = dyn + batch * 16384;  // hi; lo at +8192

    for (int i = 0; i < CPER; ++i) {
        const int st = i & 1;
        const int ph = (i >> 1) & 1;
        mbar_wait(BFULL0 + 8 * st, ph);

        const unsigned char* stg = dyn + TILE64K + st * TILE64K;  // hi; lo at +32768

        float acc[2][8][4];
#pragma unroll
        for (int mm = 0; mm < 2; ++mm)
#pragma unroll
            for (int nn = 0; nn < 8; ++nn)
#pragma unroll
                for (int q = 0; q < 4; ++q) acc[mm][nn][q] = 0.0f;

#pragma unroll
        for (int k = 0; k < 8; ++k) {
            uint4 Ah0 = *reinterpret_cast<const uint4*>(aBase + ((0 * 8 + k) * 32 + lane) * 16);
            uint4 Ah1 = *reinterpret_cast<const uint4*>(aBase + ((1 * 8 + k) * 32 + lane) * 16);
            uint4 Al0 = *reinterpret_cast<const uint4*>(aBase + 8192 + ((0 * 8 + k) * 32 + lane) * 16);
            uint4 Al1 = *reinterpret_cast<const uint4*>(aBase + 8192 + ((1 * 8 + k) * 32 + lane) * 16);
#pragma unroll
            for (int n = 0; n < 8; ++n) {
                const unsigned char* bp = stg + ((k * 16 + dhalf * 8 + n) * 32 + lane) * 8;
                uint2 Bh = *reinterpret_cast<const uint2*>(bp);
                uint2 Bl = *reinterpret_cast<const uint2*>(bp + 32768);
                mma_bf16(acc[0][n], &Ah0.x, &Bh.x);
                mma_bf16(acc[1][n], &Ah1.x, &Bh.x);
                mma_bf16(acc[0][n], &Ah0.x, &Bl.x);
                mma_bf16(acc[1][n], &Ah1.x, &Bl.x);
                mma_bf16(acc[0][n], &Al0.x, &Bh.x);
                mma_bf16(acc[1][n], &Al1.x, &Bh.x);
            }
        }

        if (lane == 0) mbar_arrive(BFREE0 + 8 * st);  // stage consumable again

        // producer: issue copy for doc i+2 into this stage
        if (tid == 0 && i + 2 < CPER) {
            mbar_wait(BFREE0 + 8 * st, ph);
            mbar_expect_tx(BFULL0 + 8 * st, TILE64K);
            bulk_copy_g2s(smem_u32(dyn + TILE64K + st * TILE64K),
                          g_P_sw + (size_t)(cbase + i + 2) * TILE64K, TILE64K,
                          BFULL0 + 8 * st);
        }

        // ---- epilogue: max over d, then cross-warp max + sum over s ----
        float m00 = -3.402823e38f, m01 = m00, m10 = m00, m11 = m00;
#pragma unroll
        for (int n = 0; n < 8; ++n) {
            m00 = fmaxf(m00, fmaxf(acc[0][n][0], acc[0][n][1]));
            m01 = fmaxf(m01, fmaxf(acc[0][n][2], acc[0][n][3]));
            m10 = fmaxf(m10, fmaxf(acc[1][n][0], acc[1][n][1]));
            m11 = fmaxf(m11, fmaxf(acc[1][n][2], acc[1][n][3]));
        }
#pragma unroll
        for (int off = 1; off <= 2; off <<= 1) {
            m00 = fmaxf(m00, __shfl_xor_sync(0xffffffffu, m00, off));
            m01 = fmaxf(m01, __shfl_xor_sync(0xffffffffu, m01, off));
            m10 = fmaxf(m10, __shfl_xor_sync(0xffffffffu, m10, off));
            m11 = fmaxf(m11, __shfl_xor_sync(0xffffffffu, m11, off));
        }
        const int buf = i & 1;
        if (tg == 0) {
            smax[buf][batch][dhalf][gr]      = m00;  // s = gr
            smax[buf][batch][dhalf][gr + 8]  = m01;  // s = gr+8
            smax[buf][batch][dhalf][gr + 16] = m10;  // s = 16+gr
            smax[buf][batch][dhalf][gr + 24] = m11;  // s = 24+gr
        }
        asm volatile("bar.sync %0, %1;" :: "r"(1 + batch), "r"(64) : "memory");
        if (dhalf == 0) {
            float v = fmaxf(smax[buf][batch][0][lane], smax[buf][batch][1][lane]);
#pragma unroll
            for (int off = 16; off; off >>= 1) v += __shfl_xor_sync(0xffffffffu, v, off);
            if (lane == 0) g_scores[b * CD + cbase + i] = v * INV_TEMP;
        }
    }
}

// ---------------------------------------------------------------------------
// loss = mean_b( logsumexp_c(scores[b,:]) - scores[b,0] )
// ---------------------------------------------------------------------------
__global__ __launch_bounds__(1024)
void loss_kernel(float* __restrict__ out) {
    const int w    = threadIdx.x >> 5;
    const int lane = threadIdx.x & 31;
    const float* row = g_scores + w * CD;

    float4 v4[4];
#pragma unroll
    for (int k = 0; k < 4; ++k)
        v4[k] = *reinterpret_cast<const float4*>(row + (lane + k * 32) * 4);

    float mx = -3.402823e38f;
#pragma unroll
    for (int k = 0; k < 4; ++k)
        mx = fmaxf(mx, fmaxf(fmaxf(v4[k].x, v4[k].y), fmaxf(v4[k].z, v4[k].w)));
#pragma unroll
    for (int off = 16; off; off >>= 1) mx = fmaxf(mx, __shfl_xor_sync(0xffffffffu, mx, off));

    float se = 0.0f;
#pragma unroll
    for (int k = 0; k < 4; ++k)
        se += expf(v4[k].x - mx) + expf(v4[k].y - mx) + expf(v4[k].z - mx) + expf(v4[k].w - mx);
#pragma unroll
    for (int off = 16; off; off >>= 1) se += __shfl_xor_sync(0xffffffffu, se, off);

    __shared__ float part[32];
    if (lane == 0) part[w] = mx + logf(se) - row[0];
    __syncthreads();

    if (w == 0) {
        float v = part[lane];
#pragma unroll
        for (int off = 16; off; off >>= 1) v += __shfl_xor_sync(0xffffffffu, v, off);
        if (lane == 0) out[0] = v * (1.0f / (float)BQ);
    }
}

extern "C" void kernel_launch(void* const* d_in, const int* in_sizes, int n_in,
                              void* d_out, int out_size) {
    const float* Q = (const float*)d_in[0];
    const float* P = (const float*)d_in[1];
    if (n_in >= 2 && in_sizes[0] != BQ * SQ * HD) {
        const float* t = Q; Q = P; P = t;
    }
    float* out = (float*)d_out;

    static bool attr_set = false;
    if (!attr_set) {
        cudaFuncSetAttribute(maxsim_kernel, cudaFuncAttributeMaxDynamicSharedMemorySize, SMEM_BYTES);
        attr_set = true;
    }

    convert_P_kernel<<<(CD * 8192 + 255) / 256, 256>>>(P);
    convert_Q_kernel<<<(NGRP * 8192 + 255) / 256, 256>>>(Q);
    maxsim_kernel<<<dim3(NCHUNK, NGRP), 256, SMEM_BYTES>>>();
    loss_kernel<<<1, 1024>>>(out);
}

// round 6
// speedup vs baseline: 3.6546x; 1.1141x over previous
#include <cuda_runtime.h>
#include <cuda_bf16.h>
#include <stdint.h>
#include <math.h>

#define BQ 32
#define SQ 32
#define HD 128
#define CD 512
#define DD 128
#define NGRP 8             // 8 groups of 4 batches (M=128 rows of A)
#define NTILE (NGRP * CD)  // 4096 (group, doc) tiles
#define NCTA 148
#define INV_TEMP 50.0f

#define TILE64K 65536
#define SMEM_BYTES (3 * TILE64K)   // A (64KB) + 2 B stages (64KB each)

__device__ float g_scores[BQ * CD];
__device__ __align__(1024) unsigned char g_P_sw[(size_t)CD * TILE64K];   // 32 MB, interleaved hi/lo B-frag
__device__ __align__(1024) unsigned char g_Q_sw[(size_t)NGRP * TILE64K]; // 512 KB, A-frag (hi | lo @ +8192)

// ---------------------------------------------------------------- PTX helpers
__device__ __forceinline__ uint32_t smem_u32(const void* p) {
    uint32_t a;
    asm("{ .reg .u64 t; cvta.to.shared.u64 t, %1; cvt.u32.u64 %0, t; }" : "=r"(a) : "l"(p));
    return a;
}
__device__ __forceinline__ void mbar_init(uint32_t m, uint32_t cnt) {
    asm volatile("mbarrier.init.shared.b64 [%0], %1;" :: "r"(m), "r"(cnt) : "memory");
}
__device__ __forceinline__ void mbar_expect_tx(uint32_t m, uint32_t bytes) {
    asm volatile("mbarrier.arrive.expect_tx.shared.b64 _, [%0], %1;" :: "r"(m), "r"(bytes) : "memory");
}
__device__ __forceinline__ void mbar_arrive(uint32_t m) {
    asm volatile("mbarrier.arrive.shared.b64 _, [%0];" :: "r"(m) : "memory");
}
__device__ __forceinline__ void mbar_wait(uint32_t m, uint32_t parity) {
    uint32_t done;
    asm volatile("{\n\t.reg .pred p;\n\t"
        "mbarrier.try_wait.parity.acquire.cta.shared::cta.b64 p, [%1], %2;\n\t"
        "selp.b32 %0, 1, 0, p;\n\t}"
        : "=r"(done) : "r"(m), "r"(parity) : "memory");
    while (!done) {
        asm volatile("{\n\t.reg .pred p;\n\t"
            "mbarrier.try_wait.parity.acquire.cta.shared::cta.b64 p, [%1], %2, 0x989680;\n\t"
            "selp.b32 %0, 1, 0, p;\n\t}"
            : "=r"(done) : "r"(m), "r"(parity) : "memory");
    }
}
__device__ __forceinline__ void bulk_copy_g2s(uint32_t dst, const void* src, uint32_t bytes, uint32_t mbar) {
    asm volatile("cp.async.bulk.shared::cluster.global.mbarrier::complete_tx::bytes [%0], [%1], %2, [%3];"
        :: "r"(dst), "l"(src), "r"(bytes), "r"(mbar) : "memory");
}
// warp mma: D(f32 16x8) += A(bf16 16x16, row) * B(bf16 16x8, col)
__device__ __forceinline__ void mma_bf16(float* c, const uint32_t* a, const uint32_t* b) {
    asm volatile("mma.sync.aligned.m16n8k16.row.col.f32.bf16.bf16.f32 "
        "{%0,%1,%2,%3}, {%4,%5,%6,%7}, {%8,%9}, {%0,%1,%2,%3};"
        : "+f"(c[0]), "+f"(c[1]), "+f"(c[2]), "+f"(c[3])
        : "r"(a[0]), "r"(a[1]), "r"(a[2]), "r"(a[3]), "r"(b[0]), "r"(b[1]));
}

__device__ __forceinline__ uint32_t bf16x2_hi(float f0, float f1, uint32_t& lo_out) {
    __nv_bfloat16 h0 = __float2bfloat16(f0);
    __nv_bfloat16 h1 = __float2bfloat16(f1);
    __nv_bfloat16 l0 = __float2bfloat16(f0 - __bfloat162float(h0));
    __nv_bfloat16 l1 = __float2bfloat16(f1 - __bfloat162float(h1));
    unsigned short uh0 = *reinterpret_cast<unsigned short*>(&h0);
    unsigned short uh1 = *reinterpret_cast<unsigned short*>(&h1);
    unsigned short ul0 = *reinterpret_cast<unsigned short*>(&l0);
    unsigned short ul1 = *reinterpret_cast<unsigned short*>(&l1);
    lo_out = (uint32_t)ul0 | ((uint32_t)ul1 << 16);
    return (uint32_t)uh0 | ((uint32_t)uh1 << 16);
}

// ---------------------------------------------------------------------------
// Combined conversion.
// P part (idx < CD*4096): per-doc 64KB tiles, one uint4 per (k,n,lane):
//   { Bhi_ri0, Bhi_ri1, Blo_ri0, Blo_ri1 } at ((k*16+n)*32+lane)*16
//   with h = k*16 + ri*8 + (lane&3)*2 {,+1}, d = n*8 + (lane>>2)
// Q part: per-group 64KB blocks, per batch 16KB { hi 8KB | lo 8KB }:
//   word at ((m*8+k)*32+lane)*16 + ri*4 holds
//   (s = m*16 + (lane>>2) + (ri&1)*8, h = k*16 + (lane&3)*2 + (ri>>1)*8 {,+1})
// ---------------------------------------------------------------------------
__global__ void convert_kernel(const float* __restrict__ P, const float* __restrict__ Q) {
    int idx = blockIdx.x * blockDim.x + threadIdx.x;
    if (idx < CD * 4096) {
        int lane = idx & 31;
        int n    = (idx >> 5) & 15;
        int k    = (idx >> 9) & 7;
        int c    = idx >> 12;
        int tg = lane & 3, gr = lane >> 2;
        int d = n * 8 + gr;

        const float* s = P + ((size_t)c * DD + d) * HD;
        uint4 v;
        uint32_t lo0, lo1;
        {
            int h = k * 16 + tg * 2;           // ri = 0
            v.x = bf16x2_hi(s[h], s[h + 1], lo0);
            h += 8;                            // ri = 1
            v.y = bf16x2_hi(s[h], s[h + 1], lo1);
        }
        v.z = lo0; v.w = lo1;
        size_t off = (size_t)c * TILE64K + (size_t)(((k * 16 + n) * 32 + lane) * 16);
        *reinterpret_cast<uint4*>(g_P_sw + off) = v;
    } else {
        int qi = idx - CD * 4096;
        if (qi >= NGRP * 8192) return;
        int ri    = qi & 3;
        int lane  = (qi >> 2) & 31;
        int k     = (qi >> 7) & 7;
        int m     = (qi >> 10) & 1;
        int batch = (qi >> 11) & 3;
        int g     = qi >> 13;
        int tg = lane & 3, gr = lane >> 2;
        int srow = m * 16 + gr + (ri & 1) * 8;
        int h    = k * 16 + tg * 2 + (ri >> 1) * 8;
        int b    = g * 4 + batch;

        const float* s = Q + ((size_t)b * SQ + srow) * HD + h;
        uint32_t lo, hi = bf16x2_hi(s[0], s[1], lo);

        size_t off = (size_t)g * TILE64K + (size_t)batch * 16384
                   + (size_t)(((m * 8 + k) * 32 + lane) * 16 + ri * 4);
        *reinterpret_cast<uint32_t*>(g_Q_sw + off)        = hi;
        *reinterpret_cast<uint32_t*>(g_Q_sw + off + 8192) = lo;
    }
}

// ---------------------------------------------------------------------------
// maxsim: persistent grid of 148 CTAs, 256 threads each. CTA i handles tile
// range [i*NTILE/NCTA, (i+1)*NTILE/NCTA); tile t -> (g = t>>9, c = t&511).
// warp w: batch = w>>1 (within group), d-half = w&1. A resident in smem
// (reloaded on the <=2 group switches); B double-buffered via cp.async.bulk.
// 3-term bf16 split: acc += Ah*Bh + Ah*Bl + Al*Bh.
// ---------------------------------------------------------------------------
__global__ __launch_bounds__(256, 1)
void maxsim_kernel() {
    extern __shared__ __align__(128) unsigned char dyn[];
    __shared__ __align__(8) unsigned long long bars[5];  // QFULL, BFULL[2], BFREE[2]
    __shared__ float smax[2][4][2][32];

    const int tid = threadIdx.x, w = tid >> 5, lane = tid & 31;
    const int batch = w >> 1, dhalf = w & 1;
    const int tg = lane & 3, gr = lane >> 2;

    const int start = (blockIdx.x * NTILE) / NCTA;
    const int end   = ((blockIdx.x + 1) * NTILE) / NCTA;
    const int L     = end - start;

    const uint32_t QFULL  = smem_u32(&bars[0]);
    const uint32_t BFULL0 = smem_u32(&bars[1]);
    const uint32_t BFREE0 = smem_u32(&bars[3]);
    const uint32_t A_S    = smem_u32(dyn);
    const uint32_t B_S    = smem_u32(dyn + TILE64K);

    if (tid == 0) {
        mbar_init(QFULL, 1);
        mbar_init(BFULL0, 1);     mbar_init(BFULL0 + 8, 1);
        mbar_init(BFREE0, 8);     mbar_init(BFREE0 + 8, 8);
    }
    __syncthreads();

    // prefetch B for j = 0, 1
    if (tid == 0) {
        mbar_expect_tx(BFULL0, TILE64K);
        bulk_copy_g2s(B_S, g_P_sw + (size_t)(start & 511) * TILE64K, TILE64K, BFULL0);
        if (L > 1) {
            mbar_expect_tx(BFULL0 + 8, TILE64K);
            bulk_copy_g2s(B_S + TILE64K, g_P_sw + (size_t)((start + 1) & 511) * TILE64K, TILE64K, BFULL0 + 8);
        }
    }

    int cur_g = -1, aloads = 0;

    for (int j = 0; j < L; ++j) {
        const int t = start + j;
        const int g = t >> 9;
        const int c = t & 511;
        const int st = j & 1;
        const int ph = (j >> 1) & 1;

        if (g != cur_g) {
            __syncthreads();  // all warps done with old A
            if (tid == 0) {
                mbar_expect_tx(QFULL, TILE64K);
                bulk_copy_g2s(A_S, g_Q_sw + (size_t)g * TILE64K, TILE64K, QFULL);
            }
            mbar_wait(QFULL, aloads & 1);
            ++aloads;
            cur_g = g;
        }

        mbar_wait(BFULL0 + 8 * st, ph);

        const unsigned char* aBase = dyn + batch * 16384;              // hi; lo at +8192
        const unsigned char* stg   = dyn + TILE64K + st * TILE64K;     // interleaved hi/lo

        float acc[2][8][4];
#pragma unroll
        for (int mm = 0; mm < 2; ++mm)
#pragma unroll
            for (int nn = 0; nn < 8; ++nn)
#pragma unroll
                for (int q = 0; q < 4; ++q) acc[mm][nn][q] = 0.0f;

#pragma unroll
        for (int k = 0; k < 8; ++k) {
            uint4 Ah0 = *reinterpret_cast<const uint4*>(aBase + ((0 * 8 + k) * 32 + lane) * 16);
            uint4 Ah1 = *reinterpret_cast<const uint4*>(aBase + ((1 * 8 + k) * 32 + lane) * 16);
            uint4 Al0 = *reinterpret_cast<const uint4*>(aBase + 8192 + ((0 * 8 + k) * 32 + lane) * 16);
            uint4 Al1 = *reinterpret_cast<const uint4*>(aBase + 8192 + ((1 * 8 + k) * 32 + lane) * 16);
#pragma unroll
            for (int n = 0; n < 8; ++n) {
                uint4 B = *reinterpret_cast<const uint4*>(
                    stg + ((k * 16 + dhalf * 8 + n) * 32 + lane) * 16);
                mma_bf16(acc[0][n], &Ah0.x, &B.x);       // Ah*Bh
                mma_bf16(acc[1][n], &Ah1.x, &B.x);
                mma_bf16(acc[0][n], &Ah0.x, &B.z);       // Ah*Bl
                mma_bf16(acc[1][n], &Ah1.x, &B.z);
                mma_bf16(acc[0][n], &Al0.x, &B.x);       // Al*Bh
                mma_bf16(acc[1][n], &Al1.x, &B.x);
            }
        }

        if (lane == 0) mbar_arrive(BFREE0 + 8 * st);  // this stage consumed

        // producer: refill this stage with doc of tile j+2
        if (tid == 0 && j + 2 < L) {
            mbar_wait(BFREE0 + 8 * st, ph);
            mbar_expect_tx(BFULL0 + 8 * st, TILE64K);
            bulk_copy_g2s(B_S + st * TILE64K,
                          g_P_sw + (size_t)((start + j + 2) & 511) * TILE64K, TILE64K,
                          BFULL0 + 8 * st);
        }

        // ---- epilogue: max over d, then cross-warp max + sum over s ----
        float m00 = -3.402823e38f, m01 = m00, m10 = m00, m11 = m00;
#pragma unroll
        for (int n = 0; n < 8; ++n) {
            m00 = fmaxf(m00, fmaxf(acc[0][n][0], acc[0][n][1]));
            m01 = fmaxf(m01, fmaxf(acc[0][n][2], acc[0][n][3]));
            m10 = fmaxf(m10, fmaxf(acc[1][n][0], acc[1][n][1]));
            m11 = fmaxf(m11, fmaxf(acc[1][n][2], acc[1][n][3]));
        }
#pragma unroll
        for (int off = 1; off <= 2; off <<= 1) {
            m00 = fmaxf(m00, __shfl_xor_sync(0xffffffffu, m00, off));
            m01 = fmaxf(m01, __shfl_xor_sync(0xffffffffu, m01, off));
            m10 = fmaxf(m10, __shfl_xor_sync(0xffffffffu, m10, off));
            m11 = fmaxf(m11, __shfl_xor_sync(0xffffffffu, m11, off));
        }
        const int buf = j & 1;
        if (tg == 0) {
            smax[buf][batch][dhalf][gr]      = m00;  // s = gr
            smax[buf][batch][dhalf][gr + 8]  = m01;  // s = gr+8
            smax[buf][batch][dhalf][gr + 16] = m10;  // s = 16+gr
            smax[buf][batch][dhalf][gr + 24] = m11;  // s = 24+gr
        }
        asm volatile("bar.sync %0, %1;" :: "r"(1 + batch), "r"(64) : "memory");
        if (dhalf == 0) {
            float v = fmaxf(smax[buf][batch][0][lane], smax[buf][batch][1][lane]);
#pragma unroll
            for (int off = 16; off; off >>= 1) v += __shfl_xor_sync(0xffffffffu, v, off);
            if (lane == 0) g_scores[(g * 4 + batch) * CD + c] = v * INV_TEMP;
        }
    }
}

// ---------------------------------------------------------------------------
// loss = mean_b( logsumexp_c(scores[b,:]) - scores[b,0] )
// ---------------------------------------------------------------------------
__global__ __launch_bounds__(1024)
void loss_kernel(float* __restrict__ out) {
    const int w    = threadIdx.x >> 5;
    const int lane = threadIdx.x & 31;
    const float* row = g_scores + w * CD;

    float4 v4[4];
#pragma unroll
    for (int k = 0; k < 4; ++k)
        v4[k] = *reinterpret_cast<const float4*>(row + (lane + k * 32) * 4);

    float mx = -3.402823e38f;
#pragma unroll
    for (int k = 0; k < 4; ++k)
        mx = fmaxf(mx, fmaxf(fmaxf(v4[k].x, v4[k].y), fmaxf(v4[k].z, v4[k].w)));
#pragma unroll
    for (int off = 16; off; off >>= 1) mx = fmaxf(mx, __shfl_xor_sync(0xffffffffu, mx, off));

    float se = 0.0f;
#pragma unroll
    for (int k = 0; k < 4; ++k)
        se += expf(v4[k].x - mx) + expf(v4[k].y - mx) + expf(v4[k].z - mx) + expf(v4[k].w - mx);
#pragma unroll
    for (int off = 16; off; off >>= 1) se += __shfl_xor_sync(0xffffffffu, se, off);

    __shared__ float part[32];
    if (lane == 0) part[w] = mx + logf(se) - row[0];
    __syncthreads();

    if (w == 0) {
        float v = part[lane];
#pragma unroll
        for (int off = 16; off; off >>= 1) v += __shfl_xor_sync(0xffffffffu, v, off);
        if (lane == 0) out[0] = v * (1.0f / (float)BQ);
    }
}

extern "C" void kernel_launch(void* const* d_in, const int* in_sizes, int n_in,
                              void* d_out, int out_size) {
    const float* Q = (const float*)d_in[0];
    const float* P = (const float*)d_in[1];
    if (n_in >= 2 && in_sizes[0] != BQ * SQ * HD) {
        const float* t = Q; Q = P; P = t;
    }
    float* out = (float*)d_out;

    static bool attr_set = false;
    if (!attr_set) {
        cudaFuncSetAttribute(maxsim_kernel, cudaFuncAttributeMaxDynamicSharedMemorySize, SMEM_BYTES);
        attr_set = true;
    }

    const int conv_total = CD * 4096 + NGRP * 8192;
    convert_kernel<<<(conv_total + 255) / 256, 256>>>(P, Q);
    maxsim_kernel<<<NCTA, 256, SMEM_BYTES>>>();
    loss_kernel<<<1, 1024>>>(out);
}